// round 7
// baseline (speedup 1.0000x reference)
#include <cuda_runtime.h>

#define HID 64

typedef unsigned long long u64;

__device__ __forceinline__ u64 pack2(float lo, float hi) {
    u64 r; asm("mov.b64 %0, {%1, %2};" : "=l"(r) : "f"(lo), "f"(hi)); return r;
}
__device__ __forceinline__ void unpack2(u64 v, float& lo, float& hi) {
    asm("mov.b64 {%0, %1}, %2;" : "=f"(lo), "=f"(hi) : "l"(v));
}
__device__ __forceinline__ void ffma2(u64& d, u64 a, u64 b) {
    asm("fma.rn.f32x2 %0, %1, %2, %0;" : "+l"(d) : "l"(a), "l"(b));
}
__device__ __forceinline__ u64 fadd2(u64 a, u64 b) {
    u64 r; asm("add.rn.f32x2 %0, %1, %2;" : "=l"(r) : "l"(a), "l"(b)); return r;
}
__device__ __forceinline__ float tanh_fast(float x) {
    return __fdividef(2.0f, 1.0f + __expf(-2.0f * x)) - 1.0f;
}

__global__ __launch_bounds__(256, 1) void decoder_lstm_kernel(
    const float* __restrict__ h0_in, const float* __restrict__ c0_in,
    const float* __restrict__ difficulty, const float* __restrict__ target,
    const float* __restrict__ W_ih0, const float* __restrict__ W_hh0,
    const float* __restrict__ b_ih0, const float* __restrict__ b_hh0,
    const float* __restrict__ W_ih1, const float* __restrict__ W_hh1,
    const float* __restrict__ b_ih1, const float* __restrict__ b_hh1,
    const float* __restrict__ W_hid, const float* __restrict__ b_hid,
    const float* __restrict__ W_out, const float* __restrict__ b_out,
    float* __restrict__ out, int T)
{
    __shared__ __align__(16) float sh_h0[HID];
    __shared__ __align__(16) float sh_h1[2][HID];   // parity double buffer
    __shared__ __align__(16) float sh_g0[256];      // activated layer0 gates (step k+1)
    __shared__ __align__(16) float sh_g1[256];      // activated layer1 gates (step k)
    __shared__ __align__(16) float sh_x[8];         // target part of x(k+1)
    __shared__ __align__(16) u64   sh_Wcp[32 * 8];  // fused head, packed pairs [kk][o]
    __shared__ float sh_bc[8];

    const int j = threadIdx.x;                     // torch gate row 0..255
    const int g = j >> 6;                          // 0=i,1=f,2=g,3=o (warp-uniform)

    // unified activation: act(x) = aa/(1+exp(-aa*x)) + ac  (sigmoid or tanh)
    const float aa = (g == 2) ? 2.0f : 1.0f;
    const float ac = (g == 2) ? -1.0f : 0.0f;

    // ---- register-resident packed recurrent weights ----
    u64 whh0p[32], wih1p[32], whh1p[32], wxp[4];
    #pragma unroll
    for (int k = 0; k < 32; k++) whh0p[k] = pack2(W_hh0[j * HID + 2 * k], W_hh0[j * HID + 2 * k + 1]);
    #pragma unroll
    for (int k = 0; k < 32; k++) wih1p[k] = pack2(W_ih1[j * HID + 2 * k], W_ih1[j * HID + 2 * k + 1]);
    #pragma unroll
    for (int k = 0; k < 32; k++) whh1p[k] = pack2(W_hh1[j * HID + 2 * k], W_hh1[j * HID + 2 * k + 1]);
    #pragma unroll
    for (int k = 0; k < 4; k++)  wxp[k]   = pack2(W_ih0[j * 14 + 2 * k], W_ih0[j * 14 + 2 * k + 1]);

    const float b0sum = b_ih0[j] + b_hh0[j];
    float dcon = b0sum;
    #pragma unroll
    for (int k = 0; k < 6; k++) dcon += difficulty[k] * W_ih0[j * 14 + 8 + k];
    const float b1c = b_ih1[j] + b_hh1[j];

    // ---- fused head Wc = W_out @ W_hid (packed pairs), bias bc ----
    {
        int kk = j >> 3, o = j & 7;
        float lo = 0.0f, hi = 0.0f;
        for (int mm = 0; mm < 32; mm++) {
            lo += W_out[o * 32 + mm] * W_hid[mm * HID + 2 * kk];
            hi += W_out[o * 32 + mm] * W_hid[mm * HID + 2 * kk + 1];
        }
        sh_Wcp[kk * 8 + o] = pack2(lo, hi);
        if (j < 8) {
            float s = b_out[j];
            for (int mm = 0; mm < 32; mm++) s += W_out[j * 32 + mm] * b_hid[mm];
            sh_bc[j] = s;
        }
    }

    // ---- initial state: c0 on tid 0-63, c1 on tid 64-127 ----
    float c0 = 0.0f, c1 = 0.0f;
    if (j < HID)             { c0 = c0_in[j]; sh_h0[j] = h0_in[j]; }
    if (j >= HID && j < 128) { c1 = c0_in[j]; sh_h1[0][j - HID] = h0_in[j]; }
    if (j < 8) sh_x[j] = target[j];   // x(1)'s target part = target[0]
    __syncthreads();

    const ulonglong2* hq0 = (const ulonglong2*)sh_h0;
    const u64*        sxq = (const u64*)sh_x;

    // ---- prologue: h0(0) from x(0)=zeros (input part = b0sum only) ----
    {
        u64 a0 = 0, a1 = 0;
        #pragma unroll
        for (int kk = 0; kk < 16; kk++) {
            ulonglong2 ha = hq0[kk];
            ffma2(a0, whh0p[2 * kk],     ha.x);
            ffma2(a1, whh0p[2 * kk + 1], ha.y);
        }
        float alo, ahi; unpack2(fadd2(a0, a1), alo, ahi);
        float g0v = b0sum + alo + ahi;
        float e = __expf(-aa * g0v);
        sh_g0[j] = __fdividef(aa, 1.0f + e) + ac;
        __syncthreads();
        if (j < HID) {
            float ai = sh_g0[j], af = sh_g0[HID + j];
            float ag = sh_g0[128 + j], ao = sh_g0[192 + j];
            c0 = af * c0 + ai * ag;
            sh_h0[j] = ao * tanh_fast(c0);   // h0(0)
        }
        __syncthreads();
    }

    // ---- main loop: iter k (p = k&1) ----
    // invariants at top: sh_h0 = h0(k), sh_h1[p] = h1(k-1), sh_x = target[k],
    //                    c0 = c0(k) [tid<64], c1 = c1(k-1) [tid 64-127]
    for (int k = 0; k < T; k++) {
        const int p = k & 1;
        const ulonglong2* hq1 = (const ulonglong2*)sh_h1[p];

        // prefetch target[k+1] (clamped) for x(k+2); committed in beta
        float xn = 0.0f;
        if ((j & ~7) == 192) {
            int tr = (k + 1 < T) ? (k + 1) : (T - 1);
            xn = target[tr * 8 + (j & 7)];
        }

        // ===== alpha: three dots (96 FFMA2), h0 loads reused =====
        u64 a0 = 0, a1 = 0, q0 = 0, q1 = 0, p0 = 0, p1 = 0;
        #pragma unroll
        for (int kk = 0; kk < 16; kk++) {
            ulonglong2 ha = hq0[kk];
            ffma2(a0, whh0p[2 * kk],     ha.x);
            ffma2(a1, whh0p[2 * kk + 1], ha.y);
            ffma2(q0, wih1p[2 * kk],     ha.x);
            ffma2(q1, wih1p[2 * kk + 1], ha.y);
            ulonglong2 hb = hq1[kk];
            ffma2(p0, whh1p[2 * kk],     hb.x);
            ffma2(p1, whh1p[2 * kk + 1], hb.y);
        }
        #pragma unroll
        for (int kk = 0; kk < 4; kk++) ffma2(a0, wxp[kk], sxq[kk]);

        float alo, ahi, glo, ghi;
        unpack2(fadd2(a0, a1), alo, ahi);
        unpack2(fadd2(fadd2(q0, q1), fadd2(p0, p1)), glo, ghi);
        float g0v = dcon + alo + ahi;         // layer0 gate, step k+1
        float g1v = b1c + glo + ghi;          // layer1 gate, step k

        float e0 = __expf(-aa * g0v);
        float e1 = __expf(-aa * g1v);
        sh_g0[j] = __fdividef(aa, 1.0f + e0) + ac;
        sh_g1[j] = __fdividef(aa, 1.0f + e1) + ac;
        __syncthreads();   // bar 1 — all warps arrive together (no straggler work)

        // ===== beta: parallel groups =====
        if (j < HID) {
            if (k < T - 1) {
                float ai = sh_g0[j], af = sh_g0[HID + j];
                float ag = sh_g0[128 + j], ao = sh_g0[192 + j];
                c0 = af * c0 + ai * ag;
                sh_h0[j] = ao * tanh_fast(c0);              // h0(k+1)
            }
        } else if (j < 128) {
            int m = j - HID;
            float ai = sh_g1[m], af = sh_g1[HID + m];
            float ag = sh_g1[128 + m], ao = sh_g1[192 + m];
            c1 = af * c1 + ai * ag;
            sh_h1[p ^ 1][m] = ao * tanh_fast(c1);           // h1(k)
        } else if (j < 160) {
            // FC head for out(k-1): warp 4 reads h1(k-1) = sh_h1[p] (stable in beta)
            int lane = j - 128, o = lane & 7, seg = lane >> 3;
            const u64* h1old = (const u64*)sh_h1[p];
            u64 f0 = 0, f1 = 0;
            #pragma unroll
            for (int kk = 0; kk < 8; kk++) {
                int idx = kk * 4 + seg;       // stride-4: conflict-free LDS.64
                ffma2((kk & 1) ? f1 : f0, sh_Wcp[idx * 8 + o], h1old[idx]);
            }
            float flo, fhi; unpack2(fadd2(f0, f1), flo, fhi);
            float part = flo + fhi;
            part += __shfl_xor_sync(0xffffffffu, part, 8);
            part += __shfl_xor_sync(0xffffffffu, part, 16);
            if (seg == 0 && k > 0)
                out[(k - 1) * 8 + o] = rintf(sh_bc[o] + part);
        } else if ((j & ~7) == 192) {
            sh_x[j & 7] = xn;                               // target[k+1] -> x(k+2)
        }
        __syncthreads();   // bar 2
    }

    // ---- epilogue: out(T-1) from sh_h1[T&1] = h1(T-1), then finals ----
    const int pe = T & 1;
    const u64* h1f = (const u64*)sh_h1[pe];
    if (j < 8) {
        u64 f0 = 0, f1 = 0;
        #pragma unroll
        for (int kk = 0; kk < 32; kk++)
            ffma2((kk & 1) ? f1 : f0, sh_Wcp[kk * 8 + j], h1f[kk]);
        float flo, fhi; unpack2(fadd2(f0, f1), flo, fhi);
        out[(T - 1) * 8 + j] = rintf(sh_bc[j] + flo + fhi);
    }
    // finals: h_final = [h0(T-1); h1(T-1)], c_final = [c0(T-1); c1(T-1)]
    if (j < HID) {
        out[T * 8 + j]       = sh_h0[j];
        out[T * 8 + 128 + j] = c0;
    }
    if (j >= HID && j < 128) {
        out[T * 8 + j]       = sh_h1[pe][j - HID];
        out[T * 8 + 128 + j] = c1;
    }
}

extern "C" void kernel_launch(void* const* d_in, const int* in_sizes, int n_in,
                              void* d_out, int out_size) {
    const float* h0_in  = (const float*)d_in[1];
    const float* c0_in  = (const float*)d_in[2];
    const float* diff   = (const float*)d_in[3];
    const float* target = (const float*)d_in[4];
    const float* W_ih0  = (const float*)d_in[5];
    const float* W_hh0  = (const float*)d_in[6];
    const float* b_ih0  = (const float*)d_in[7];
    const float* b_hh0  = (const float*)d_in[8];
    const float* W_ih1  = (const float*)d_in[9];
    const float* W_hh1  = (const float*)d_in[10];
    const float* b_ih1  = (const float*)d_in[11];
    const float* b_hh1  = (const float*)d_in[12];
    const float* W_hid  = (const float*)d_in[13];
    const float* b_hid  = (const float*)d_in[14];
    const float* W_out  = (const float*)d_in[15];
    const float* b_out  = (const float*)d_in[16];

    int T = in_sizes[4] / 8;

    decoder_lstm_kernel<<<1, 256>>>(
        h0_in, c0_in, diff, target,
        W_ih0, W_hh0, b_ih0, b_hh0,
        W_ih1, W_hh1, b_ih1, b_hh1,
        W_hid, b_hid, W_out, b_out,
        (float*)d_out, T);
}

// round 8
// speedup vs baseline: 1.0102x; 1.0102x over previous
#include <cuda_runtime.h>

#define HID 64
#define GATES 256
#define IN8 8

typedef unsigned long long u64;

__device__ __forceinline__ u64 pack2(float lo, float hi) {
    u64 r; asm("mov.b64 %0, {%1, %2};" : "=l"(r) : "f"(lo), "f"(hi)); return r;
}
__device__ __forceinline__ void unpack2(u64 v, float& lo, float& hi) {
    asm("mov.b64 {%0, %1}, %2;" : "=f"(lo), "=f"(hi) : "l"(v));
}
__device__ __forceinline__ void ffma2(u64& d, u64 a, u64 b) {
    asm("fma.rn.f32x2 %0, %1, %2, %0;" : "+l"(d) : "l"(a), "l"(b));
}
__device__ __forceinline__ u64 fadd2(u64 a, u64 b) {
    u64 r; asm("add.rn.f32x2 %0, %1, %2;" : "=l"(r) : "l"(a), "l"(b)); return r;
}

__device__ __forceinline__ float sigf(float x) {
    return __fdividef(1.0f, 1.0f + __expf(-x));
}
__device__ __forceinline__ float tanh_fast(float x) {
    return __fdividef(2.0f, 1.0f + __expf(-2.0f * x)) - 1.0f;
}

__global__ __launch_bounds__(256, 1) void decoder_lstm_kernel(
    const float* __restrict__ h0_in, const float* __restrict__ c0_in,
    const float* __restrict__ difficulty, const float* __restrict__ target,
    const float* __restrict__ W_ih0, const float* __restrict__ W_hh0,
    const float* __restrict__ b_ih0, const float* __restrict__ b_hh0,
    const float* __restrict__ W_ih1, const float* __restrict__ W_hh1,
    const float* __restrict__ b_ih1, const float* __restrict__ b_hh1,
    const float* __restrict__ W_hid, const float* __restrict__ b_hid,
    const float* __restrict__ W_out, const float* __restrict__ b_out,
    float* __restrict__ out, int T)
{
    __shared__ __align__(16) float sh_h0[HID];
    __shared__ __align__(16) float sh_h1[HID];
    __shared__ __align__(16) float sh_g0[256];      // activated layer0 gates (step t+1)
    __shared__ __align__(16) float sh_g1[256];      // activated layer1 gates (step t)
    __shared__ __align__(16) float sh_x[IN8];       // target part of x(t+1)
    __shared__ __align__(16) u64   sh_Wcp[32 * 8];  // fused head, packed pairs: [kk][o]
    __shared__ float sh_bc[8];
    __shared__ float sh_fcp[16];                    // FC partials (2 halves x 8 outputs)

    const int j = threadIdx.x;
    const bool gate_is_g = (j >= 128 && j < 192);   // tanh gate (warp-uniform)
    const int  wpar = (j >> 5) & 1;                 // warp parity: de-phase SMSP partners

    // ---- one-time init: register-resident packed recurrent weights ----
    u64 whh0p[32], wih1p[32], whh1p[32], wxp[4];
    #pragma unroll
    for (int k = 0; k < 32; k++) whh0p[k] = pack2(W_hh0[j * HID + 2 * k], W_hh0[j * HID + 2 * k + 1]);
    #pragma unroll
    for (int k = 0; k < 32; k++) wih1p[k] = pack2(W_ih1[j * HID + 2 * k], W_ih1[j * HID + 2 * k + 1]);
    #pragma unroll
    for (int k = 0; k < 32; k++) whh1p[k] = pack2(W_hh1[j * HID + 2 * k], W_hh1[j * HID + 2 * k + 1]);
    #pragma unroll
    for (int k = 0; k < 4; k++)  wxp[k]   = pack2(W_ih0[j * 14 + 2 * k], W_ih0[j * 14 + 2 * k + 1]);

    const float b0sum = b_ih0[j] + b_hh0[j];
    float dcon = b0sum;
    #pragma unroll
    for (int k = 0; k < 6; k++) dcon += difficulty[k] * W_ih0[j * 14 + 8 + k];
    const float b1c = b_ih1[j] + b_hh1[j];

    // ---- fused head Wc = W_out @ W_hid, packed pairs, layout [kk][o] ----
    {
        int kk = j >> 3, o = j & 7;
        float lo = 0.0f, hi = 0.0f;
        for (int m = 0; m < 32; m++) {
            lo += W_out[o * 32 + m] * W_hid[m * HID + 2 * kk];
            hi += W_out[o * 32 + m] * W_hid[m * HID + 2 * kk + 1];
        }
        sh_Wcp[kk * 8 + o] = pack2(lo, hi);
        if (j < 8) {
            float s = b_out[j];
            for (int m = 0; m < 32; m++) s += W_out[j * 32 + m] * b_hid[m];
            sh_bc[j] = s;
        }
    }

    // ---- initial state: c0 in tid 0-63, c1 in tid 64-127 ----
    float c0 = 0.0f, c1 = 0.0f;
    if (j < HID)             { c0 = c0_in[j]; sh_h0[j] = h0_in[j]; }
    if (j >= HID && j < 128) { c1 = c0_in[j]; sh_h1[j - HID] = h0_in[j]; }
    if (j < 8) sh_x[j] = target[j];   // x(1)'s target part = target[0]
    __syncthreads();

    const ulonglong2* hq0 = (const ulonglong2*)sh_h0;
    const ulonglong2* hq1 = (const ulonglong2*)sh_h1;
    const u64*        sxq = (const u64*)sh_x;
    const u64*        h1q = (const u64*)sh_h1;

    // ---- prologue: layer0 of step 0 (x(0) = zeros -> bias-only input part) ----
    {
        u64 a0 = 0, a1 = 0;
        #pragma unroll
        for (int k = 0; k < 16; k++) {
            ulonglong2 ha = hq0[k];
            ffma2(a0, whh0p[2 * k],     ha.x);
            ffma2(a1, whh0p[2 * k + 1], ha.y);
        }
        float alo, ahi; unpack2(fadd2(a0, a1), alo, ahi);
        float g0 = b0sum + alo + ahi;
        sh_g0[j] = gate_is_g ? tanh_fast(g0) : sigf(g0);
        __syncthreads();
        if (j < HID) {
            float ai = sh_g0[j], af = sh_g0[HID + j];
            float ag = sh_g0[128 + j], ao = sh_g0[192 + j];
            c0 = af * c0 + ai * ag;
            sh_h0[j] = ao * tanh_fast(c0);   // h0(0)
        }
        __syncthreads();
    }

    // ---- main loop: iteration k does layer1(k) + layer0(k+1) + out(k-1) ----
    // invariants at top: sh_h0 = h0(k), sh_h1 = h1(k-1), sh_x = target[k],
    //                    c0 = c0(k) (tid<64), c1 = c1(k-1) (tid 64-127)
    for (int k = 0; k < T; k++) {
        // prefetch target[k+1] (clamped) for x(k+2)
        float xn = 0.0f;
        if ((j & ~7) == 192) {
            int tr = (k + 1 < T) ? (k + 1) : (T - 1);
            xn = target[tr * 8 + (j & 7)];
        }

        // ===== Phase alpha: both gate dots; ODD warps iterate in reverse =====
        // (de-phases LDS-stall windows of the two co-resident warps per SMSP)
        u64 a0 = 0, a1 = 0, q0 = 0, q1 = 0, p0 = 0, p1 = 0;
        if (wpar == 0) {
            #pragma unroll
            for (int kk = 0; kk < 16; kk++) {
                ulonglong2 ha = hq0[kk];
                ffma2(a0, whh0p[2 * kk],     ha.x);
                ffma2(a1, whh0p[2 * kk + 1], ha.y);
                ffma2(q0, wih1p[2 * kk],     ha.x);
                ffma2(q1, wih1p[2 * kk + 1], ha.y);
                ulonglong2 hb = hq1[kk];
                ffma2(p0, whh1p[2 * kk],     hb.x);
                ffma2(p1, whh1p[2 * kk + 1], hb.y);
            }
        } else {
            #pragma unroll
            for (int kk = 15; kk >= 0; kk--) {
                ulonglong2 ha = hq0[kk];
                ffma2(a0, whh0p[2 * kk],     ha.x);
                ffma2(a1, whh0p[2 * kk + 1], ha.y);
                ffma2(q0, wih1p[2 * kk],     ha.x);
                ffma2(q1, wih1p[2 * kk + 1], ha.y);
                ulonglong2 hb = hq1[kk];
                ffma2(p0, whh1p[2 * kk],     hb.x);
                ffma2(p1, whh1p[2 * kk + 1], hb.y);
            }
        }
        #pragma unroll
        for (int kk = 0; kk < 4; kk++) ffma2(a0, wxp[kk], sxq[kk]);

        float alo, ahi, glo, ghi;
        unpack2(fadd2(a0, a1), alo, ahi);
        unpack2(fadd2(fadd2(q0, q1), fadd2(p0, p1)), glo, ghi);
        float g0 = dcon + alo + ahi;          // layer0 gate, step k+1
        float g1 = b1c + glo + ghi;           // layer1 gate, step k

        sh_g0[j] = gate_is_g ? tanh_fast(g0) : sigf(g0);
        sh_g1[j] = gate_is_g ? tanh_fast(g1) : sigf(g1);

        // FC head partials for out(k-1), reads sh_h1 = h1(k-1)
        if ((j & ~15) == 224) {
            int o = j & 7, half = (j >> 3) & 1;
            u64 f0 = 0, f1 = 0;
            #pragma unroll
            for (int kk = 0; kk < 16; kk++) {
                int idx = half * 16 + kk;
                ffma2((kk & 1) ? f1 : f0, sh_Wcp[idx * 8 + o], h1q[idx]);
            }
            float flo, fhi; unpack2(fadd2(f0, f1), flo, fhi);
            sh_fcp[half * 8 + o] = flo + fhi;
        }
        __syncthreads();   // bar 1

        // ===== Phase beta: state updates (parallel across thread groups) =====
        if (j < HID) {
            if (k < T - 1) {   // last iteration's layer0 result (step T) is discarded
                float ai = sh_g0[j], af = sh_g0[HID + j];
                float ag = sh_g0[128 + j], ao = sh_g0[192 + j];
                c0 = af * c0 + ai * ag;
                sh_h0[j] = ao * tanh_fast(c0);      // h0(k+1)
            }
        } else if (j < 128) {
            int m = j - HID;
            float ai = sh_g1[m], af = sh_g1[HID + m];
            float ag = sh_g1[128 + m], ao = sh_g1[192 + m];
            c1 = af * c1 + ai * ag;
            sh_h1[m] = ao * tanh_fast(c1);          // h1(k)
        } else if (j < 136) {
            if (k > 0) {
                int o = j - 128;
                float s = sh_bc[o] + sh_fcp[o] + sh_fcp[8 + o];
                out[(k - 1) * 8 + o] = rintf(s);
            }
        } else if ((j & ~7) == 192) {
            sh_x[j & 7] = xn;                       // target[k+1] -> x(k+2)
        }
        __syncthreads();   // bar 2
    }

    // ---- epilogue: out[T-1] from sh_h1 = h1(T-1), then finals ----
    if (j < 8) {
        u64 acc0 = 0, acc1 = 0;
        #pragma unroll
        for (int kk = 0; kk < 32; kk++)
            ffma2((kk & 1) ? acc1 : acc0, sh_Wcp[kk * 8 + j], h1q[kk]);
        float flo, fhi; unpack2(fadd2(acc0, acc1), flo, fhi);
        out[(T - 1) * 8 + j] = rintf(sh_bc[j] + flo + fhi);
    }
    // finals: h_final = [h0(T-1); h1(T-1)], c_final = [c0(T-1); c1(T-1)]
    if (j < HID) {
        out[T * 8 + j]       = sh_h0[j];
        out[T * 8 + HID + j] = sh_h1[j];
        out[T * 8 + 128 + j] = c0;
    }
    if (j >= HID && j < 128) {
        out[T * 8 + 192 + (j - HID)] = c1;
    }
}

extern "C" void kernel_launch(void* const* d_in, const int* in_sizes, int n_in,
                              void* d_out, int out_size) {
    const float* h0_in  = (const float*)d_in[1];
    const float* c0_in  = (const float*)d_in[2];
    const float* diff   = (const float*)d_in[3];
    const float* target = (const float*)d_in[4];
    const float* W_ih0  = (const float*)d_in[5];
    const float* W_hh0  = (const float*)d_in[6];
    const float* b_ih0  = (const float*)d_in[7];
    const float* b_hh0  = (const float*)d_in[8];
    const float* W_ih1  = (const float*)d_in[9];
    const float* W_hh1  = (const float*)d_in[10];
    const float* b_ih1  = (const float*)d_in[11];
    const float* b_hh1  = (const float*)d_in[12];
    const float* W_hid  = (const float*)d_in[13];
    const float* b_hid  = (const float*)d_in[14];
    const float* W_out  = (const float*)d_in[15];
    const float* b_out  = (const float*)d_in[16];

    int T = in_sizes[4] / 8;

    decoder_lstm_kernel<<<1, 256>>>(
        h0_in, c0_in, diff, target,
        W_ih0, W_hh0, b_ih0, b_hh0,
        W_ih1, W_hh1, b_ih1, b_hh1,
        W_hid, b_hid, W_out, b_out,
        (float*)d_out, T);
}

// round 9
// speedup vs baseline: 1.0650x; 1.0542x over previous
#include <cuda_runtime.h>

#define HID 64

typedef unsigned long long u64;

__device__ __forceinline__ u64 pack2(float lo, float hi) {
    u64 r; asm("mov.b64 %0, {%1, %2};" : "=l"(r) : "f"(lo), "f"(hi)); return r;
}
__device__ __forceinline__ void unpack2(u64 v, float& lo, float& hi) {
    asm("mov.b64 {%0, %1}, %2;" : "=f"(lo), "=f"(hi) : "l"(v));
}
__device__ __forceinline__ void ffma2(u64& d, u64 a, u64 b) {
    asm("fma.rn.f32x2 %0, %1, %2, %0;" : "+l"(d) : "l"(a), "l"(b));
}
__device__ __forceinline__ u64 fadd2(u64 a, u64 b) {
    u64 r; asm("add.rn.f32x2 %0, %1, %2;" : "=l"(r) : "l"(a), "l"(b)); return r;
}

__device__ __forceinline__ float sigf(float x) {
    return __fdividef(1.0f, 1.0f + __expf(-x));
}
__device__ __forceinline__ float tanh_fast(float x) {
    return __fdividef(2.0f, 1.0f + __expf(-2.0f * x)) - 1.0f;
}

__global__ __launch_bounds__(256, 1) void decoder_lstm_kernel(
    const float* __restrict__ h0_in, const float* __restrict__ c0_in,
    const float* __restrict__ difficulty, const float* __restrict__ target,
    const float* __restrict__ W_ih0, const float* __restrict__ W_hh0,
    const float* __restrict__ b_ih0, const float* __restrict__ b_hh0,
    const float* __restrict__ W_ih1, const float* __restrict__ W_hh1,
    const float* __restrict__ b_ih1, const float* __restrict__ b_hh1,
    const float* __restrict__ W_hid, const float* __restrict__ b_hid,
    const float* __restrict__ W_out, const float* __restrict__ b_out,
    float* __restrict__ out, int T)
{
    __shared__ __align__(16) float sh_h0[HID];
    __shared__ __align__(16) float sh_h1[HID];
    __shared__ __align__(16) float sh_g0[256];      // activated layer0 gates (step t+1)
    __shared__ __align__(16) float sh_g1[256];      // activated layer1 gates (step t)
    __shared__ __align__(16) float sh_x[8];         // target part of x(t+1)
    __shared__ __align__(16) u64   sh_Wcp[32 * 8];  // fused head, packed pairs: [kk][o]
    __shared__ float sh_bc[8];
    __shared__ float sh_fcp[16];                    // FC partials (2 halves x 8 outputs)

    const int j = threadIdx.x;
    const bool gate_is_g = (j >= 128 && j < 192);   // tanh gate (warp-uniform)

    // ---- one-time init: register-resident packed recurrent weights ----
    u64 whh0p[32], wih1p[32], whh1p[32], wxp[4];
    #pragma unroll
    for (int k = 0; k < 32; k++) whh0p[k] = pack2(W_hh0[j * HID + 2 * k], W_hh0[j * HID + 2 * k + 1]);
    #pragma unroll
    for (int k = 0; k < 32; k++) wih1p[k] = pack2(W_ih1[j * HID + 2 * k], W_ih1[j * HID + 2 * k + 1]);
    #pragma unroll
    for (int k = 0; k < 32; k++) whh1p[k] = pack2(W_hh1[j * HID + 2 * k], W_hh1[j * HID + 2 * k + 1]);
    #pragma unroll
    for (int k = 0; k < 4; k++)  wxp[k]   = pack2(W_ih0[j * 14 + 2 * k], W_ih0[j * 14 + 2 * k + 1]);

    const float b0sum = b_ih0[j] + b_hh0[j];
    float dcon = b0sum;
    #pragma unroll
    for (int k = 0; k < 6; k++) dcon += difficulty[k] * W_ih0[j * 14 + 8 + k];
    const float b1c = b_ih1[j] + b_hh1[j];

    // ---- fused head Wc = W_out @ W_hid, packed pairs, layout [kk][o] ----
    {
        int kk = j >> 3, o = j & 7;
        float lo = 0.0f, hi = 0.0f;
        for (int m = 0; m < 32; m++) {
            lo += W_out[o * 32 + m] * W_hid[m * HID + 2 * kk];
            hi += W_out[o * 32 + m] * W_hid[m * HID + 2 * kk + 1];
        }
        sh_Wcp[kk * 8 + o] = pack2(lo, hi);
        if (j < 8) {
            float s = b_out[j];
            for (int m = 0; m < 32; m++) s += W_out[j * 32 + m] * b_hid[m];
            sh_bc[j] = s;
        }
    }

    // ---- initial state: c0 in tid 0-63, c1 in tid 64-127 ----
    float c0 = 0.0f, c1 = 0.0f;
    if (j < HID)             { c0 = c0_in[j]; sh_h0[j] = h0_in[j]; }
    if (j >= HID && j < 128) { c1 = c0_in[j]; sh_h1[j - HID] = h0_in[j]; }
    if (j < 8) sh_x[j] = target[j];   // x(1)'s target part = target[0]
    __syncthreads();

    const ulonglong2* hq0 = (const ulonglong2*)sh_h0;
    const ulonglong2* hq1 = (const ulonglong2*)sh_h1;
    const u64*        sxq = (const u64*)sh_x;
    const u64*        h1q = (const u64*)sh_h1;

    // ---- prologue: layer0 of step 0 (x(0) = zeros -> bias-only input part) ----
    {
        u64 a0 = 0, a1 = 0;
        #pragma unroll
        for (int k = 0; k < 16; k++) {
            ulonglong2 ha = hq0[k];
            ffma2(a0, whh0p[2 * k],     ha.x);
            ffma2(a1, whh0p[2 * k + 1], ha.y);
        }
        float alo, ahi; unpack2(fadd2(a0, a1), alo, ahi);
        float g0 = b0sum + alo + ahi;
        sh_g0[j] = gate_is_g ? tanh_fast(g0) : sigf(g0);
        __syncthreads();
        if (j < HID) {
            float ai = sh_g0[j], af = sh_g0[HID + j];
            float ag = sh_g0[128 + j], ao = sh_g0[192 + j];
            c0 = af * c0 + ai * ag;
            sh_h0[j] = ao * tanh_fast(c0);   // h0(0)
        }
        __syncthreads();
    }

    // ---- main loop: iteration k does layer1(k) + layer0(k+1) + out(k-1) ----
    // invariants at top: sh_h0 = h0(k), sh_h1 = h1(k-1), sh_x = target[k],
    //                    c0 = c0(k) (tid<64), c1 = c1(k-1) (tid 64-127)
    for (int k = 0; k < T; k++) {
        // prefetch target[k+1] (clamped) for x(k+2)
        float xn = 0.0f;
        if ((j & ~7) == 192) {
            int tr = (k + 1 < T) ? (k + 1) : (T - 1);
            xn = target[tr * 8 + (j & 7)];
        }

        // ===== Phase alpha: both gate dots, explicit load double-buffering =====
        u64 a0 = 0, a1 = 0, q0 = 0, q1 = 0, p0 = 0, p1 = 0;
        {
            ulonglong2 ha = hq0[0];
            ulonglong2 hb = hq1[0];
            #pragma unroll
            for (int kk = 0; kk < 16; kk++) {
                ulonglong2 ha_n, hb_n;
                if (kk < 15) {                 // compile-time guard (fully unrolled)
                    ha_n = hq0[kk + 1];        // issue next loads BEFORE using current
                    hb_n = hq1[kk + 1];
                }
                ffma2(a0, whh0p[2 * kk],     ha.x);
                ffma2(a1, whh0p[2 * kk + 1], ha.y);
                ffma2(q0, wih1p[2 * kk],     ha.x);
                ffma2(q1, wih1p[2 * kk + 1], ha.y);
                ffma2(p0, whh1p[2 * kk],     hb.x);
                ffma2(p1, whh1p[2 * kk + 1], hb.y);
                if (kk < 15) { ha = ha_n; hb = hb_n; }
            }
        }
        #pragma unroll
        for (int kk = 0; kk < 4; kk++) ffma2(a0, wxp[kk], sxq[kk]);

        float alo, ahi, glo, ghi;
        unpack2(fadd2(a0, a1), alo, ahi);
        unpack2(fadd2(fadd2(q0, q1), fadd2(p0, p1)), glo, ghi);
        float g0 = dcon + alo + ahi;          // layer0 gate, step k+1
        float g1 = b1c + glo + ghi;           // layer1 gate, step k

        sh_g0[j] = gate_is_g ? tanh_fast(g0) : sigf(g0);
        sh_g1[j] = gate_is_g ? tanh_fast(g1) : sigf(g1);

        // FC head partials for out(k-1), reads sh_h1 = h1(k-1)
        if ((j & ~15) == 224) {
            int o = j & 7, half = (j >> 3) & 1;
            u64 f0 = 0, f1 = 0;
            #pragma unroll
            for (int kk = 0; kk < 16; kk++) {
                int idx = half * 16 + kk;
                ffma2((kk & 1) ? f1 : f0, sh_Wcp[idx * 8 + o], h1q[idx]);
            }
            float flo, fhi; unpack2(fadd2(f0, f1), flo, fhi);
            sh_fcp[half * 8 + o] = flo + fhi;
        }
        __syncthreads();   // bar 1

        // ===== Phase beta: state updates (parallel across thread groups) =====
        if (j < HID) {
            if (k < T - 1) {   // last iteration's layer0 result (step T) is discarded
                float ai = sh_g0[j], af = sh_g0[HID + j];
                float ag = sh_g0[128 + j], ao = sh_g0[192 + j];
                c0 = af * c0 + ai * ag;
                sh_h0[j] = ao * tanh_fast(c0);      // h0(k+1)
            }
        } else if (j < 128) {
            int m = j - HID;
            float ai = sh_g1[m], af = sh_g1[HID + m];
            float ag = sh_g1[128 + m], ao = sh_g1[192 + m];
            c1 = af * c1 + ai * ag;
            sh_h1[m] = ao * tanh_fast(c1);          // h1(k)
        } else if (j < 136) {
            if (k > 0) {
                int o = j - 128;
                float s = sh_bc[o] + sh_fcp[o] + sh_fcp[8 + o];
                out[(k - 1) * 8 + o] = rintf(s);
            }
        } else if ((j & ~7) == 192) {
            sh_x[j & 7] = xn;                       // target[k+1] -> x(k+2)
        }
        __syncthreads();   // bar 2
    }

    // ---- epilogue: out[T-1] from sh_h1 = h1(T-1), then finals ----
    if (j < 8) {
        u64 acc0 = 0, acc1 = 0;
        #pragma unroll
        for (int kk = 0; kk < 32; kk++)
            ffma2((kk & 1) ? acc1 : acc0, sh_Wcp[kk * 8 + j], h1q[kk]);
        float flo, fhi; unpack2(fadd2(acc0, acc1), flo, fhi);
        out[(T - 1) * 8 + j] = rintf(sh_bc[j] + flo + fhi);
    }
    // finals: h_final = [h0(T-1); h1(T-1)], c_final = [c0(T-1); c1(T-1)]
    if (j < HID) {
        out[T * 8 + j]       = sh_h0[j];
        out[T * 8 + HID + j] = sh_h1[j];
        out[T * 8 + 128 + j] = c0;
    }
    if (j >= HID && j < 128) {
        out[T * 8 + 192 + (j - HID)] = c1;
    }
}

extern "C" void kernel_launch(void* const* d_in, const int* in_sizes, int n_in,
                              void* d_out, int out_size) {
    const float* h0_in  = (const float*)d_in[1];
    const float* c0_in  = (const float*)d_in[2];
    const float* diff   = (const float*)d_in[3];
    const float* target = (const float*)d_in[4];
    const float* W_ih0  = (const float*)d_in[5];
    const float* W_hh0  = (const float*)d_in[6];
    const float* b_ih0  = (const float*)d_in[7];
    const float* b_hh0  = (const float*)d_in[8];
    const float* W_ih1  = (const float*)d_in[9];
    const float* W_hh1  = (const float*)d_in[10];
    const float* b_ih1  = (const float*)d_in[11];
    const float* b_hh1  = (const float*)d_in[12];
    const float* W_hid  = (const float*)d_in[13];
    const float* b_hid  = (const float*)d_in[14];
    const float* W_out  = (const float*)d_in[15];
    const float* b_out  = (const float*)d_in[16];

    int T = in_sizes[4] / 8;

    decoder_lstm_kernel<<<1, 256>>>(
        h0_in, c0_in, diff, target,
        W_ih0, W_hh0, b_ih0, b_hh0,
        W_ih1, W_hh1, b_ih1, b_hh1,
        W_hid, b_hid, W_out, b_out,
        (float*)d_out, T);
}

// round 10
// speedup vs baseline: 1.1699x; 1.0985x over previous
#include <cuda_runtime.h>

#define HID 64

typedef unsigned long long u64;

__device__ __forceinline__ u64 pack2(float lo, float hi) {
    u64 r; asm("mov.b64 %0, {%1, %2};" : "=l"(r) : "f"(lo), "f"(hi)); return r;
}
__device__ __forceinline__ void unpack2(u64 v, float& lo, float& hi) {
    asm("mov.b64 {%0, %1}, %2;" : "=f"(lo), "=f"(hi) : "l"(v));
}
__device__ __forceinline__ void ffma2(u64& d, u64 a, u64 b) {
    asm("fma.rn.f32x2 %0, %1, %2, %0;" : "+l"(d) : "l"(a), "l"(b));
}
__device__ __forceinline__ u64 fadd2(u64 a, u64 b) {
    u64 r; asm("add.rn.f32x2 %0, %1, %2;" : "=l"(r) : "l"(a), "l"(b)); return r;
}

__device__ __forceinline__ float sigf(float x) {
    return __fdividef(1.0f, 1.0f + __expf(-x));
}
__device__ __forceinline__ float tanh_fast(float x) {
    return __fdividef(2.0f, 1.0f + __expf(-2.0f * x)) - 1.0f;
}

__global__ __launch_bounds__(256, 1) void decoder_lstm_kernel(
    const float* __restrict__ h0_in, const float* __restrict__ c0_in,
    const float* __restrict__ difficulty, const float* __restrict__ target,
    const float* __restrict__ W_ih0, const float* __restrict__ W_hh0,
    const float* __restrict__ b_ih0, const float* __restrict__ b_hh0,
    const float* __restrict__ W_ih1, const float* __restrict__ W_hh1,
    const float* __restrict__ b_ih1, const float* __restrict__ b_hh1,
    const float* __restrict__ W_hid, const float* __restrict__ b_hid,
    const float* __restrict__ W_out, const float* __restrict__ b_out,
    float* __restrict__ out, int T)
{
    __shared__ __align__(16) float sh_h0[HID];
    __shared__ __align__(16) float sh_h1[HID];
    __shared__ __align__(16) float sh_g0[256];      // activated layer0 gates (step t+1)
    __shared__ __align__(16) float sh_g1[256];      // activated layer1 gates (step t)
    __shared__ __align__(16) float sh_x[8];         // target part of x(t+1)
    __shared__ __align__(16) u64   sh_Wcp[32 * 8];  // fused head, packed pairs: [kk][o]
    __shared__ float sh_bc[8];
    __shared__ float sh_fcp[32];                    // FC partials (4 segs x 8 outputs)

    const int j = threadIdx.x;
    const bool gate_is_g = (j >= 128 && j < 192);   // tanh gate (warp-uniform)

    // ---- one-time init: register-resident packed recurrent weights ----
    u64 whh0p[32], wih1p[32], whh1p[32], wxp[4];
    #pragma unroll
    for (int k = 0; k < 32; k++) whh0p[k] = pack2(W_hh0[j * HID + 2 * k], W_hh0[j * HID + 2 * k + 1]);
    #pragma unroll
    for (int k = 0; k < 32; k++) wih1p[k] = pack2(W_ih1[j * HID + 2 * k], W_ih1[j * HID + 2 * k + 1]);
    #pragma unroll
    for (int k = 0; k < 32; k++) whh1p[k] = pack2(W_hh1[j * HID + 2 * k], W_hh1[j * HID + 2 * k + 1]);
    #pragma unroll
    for (int k = 0; k < 4; k++)  wxp[k]   = pack2(W_ih0[j * 14 + 2 * k], W_ih0[j * 14 + 2 * k + 1]);

    const float b0sum = b_ih0[j] + b_hh0[j];
    float dcon = b0sum;
    #pragma unroll
    for (int k = 0; k < 6; k++) dcon += difficulty[k] * W_ih0[j * 14 + 8 + k];
    const float b1c = b_ih1[j] + b_hh1[j];

    // ---- fused head Wc = W_out @ W_hid, packed pairs, layout [kk][o] ----
    {
        int kk = j >> 3, o = j & 7;
        float lo = 0.0f, hi = 0.0f;
        for (int m = 0; m < 32; m++) {
            lo += W_out[o * 32 + m] * W_hid[m * HID + 2 * kk];
            hi += W_out[o * 32 + m] * W_hid[m * HID + 2 * kk + 1];
        }
        sh_Wcp[kk * 8 + o] = pack2(lo, hi);
        if (j < 8) {
            float s = b_out[j];
            for (int m = 0; m < 32; m++) s += W_out[j * 32 + m] * b_hid[m];
            sh_bc[j] = s;
        }
    }

    // ---- initial state: c0 in tid 0-63, c1 in tid 64-127 ----
    float c0 = 0.0f, c1 = 0.0f;
    if (j < HID)             { c0 = c0_in[j]; sh_h0[j] = h0_in[j]; }
    if (j >= HID && j < 128) { c1 = c0_in[j]; sh_h1[j - HID] = h0_in[j]; }
    if (j < 8) sh_x[j] = target[j];   // x(1)'s target part = target[0]
    __syncthreads();

    const ulonglong2* hq0 = (const ulonglong2*)sh_h0;
    const ulonglong2* hq1 = (const ulonglong2*)sh_h1;
    const u64*        sxq = (const u64*)sh_x;
    const u64*        h1q = (const u64*)sh_h1;

    // ---- prologue: layer0 of step 0 (x(0) = zeros -> bias-only input part) ----
    {
        u64 a0 = 0, a1 = 0;
        #pragma unroll
        for (int k = 0; k < 16; k++) {
            ulonglong2 ha = hq0[k];
            ffma2(a0, whh0p[2 * k],     ha.x);
            ffma2(a1, whh0p[2 * k + 1], ha.y);
        }
        float alo, ahi; unpack2(fadd2(a0, a1), alo, ahi);
        float g0 = b0sum + alo + ahi;
        sh_g0[j] = gate_is_g ? tanh_fast(g0) : sigf(g0);
        __syncthreads();
        if (j < HID) {
            float ai = sh_g0[j], af = sh_g0[HID + j];
            float ag = sh_g0[128 + j], ao = sh_g0[192 + j];
            c0 = af * c0 + ai * ag;
            sh_h0[j] = ao * tanh_fast(c0);   // h0(0)
        }
        __syncthreads();
    }

    // ---- main loop: k = 0..T-2 (final iteration peeled; no per-iter guards on
    //      the h0 update or the xn clamp) ----
    // invariants at top: sh_h0 = h0(k), sh_h1 = h1(k-1), sh_x = target[k],
    //                    c0 = c0(k) (tid<64), c1 = c1(k-1) (tid 64-127)
    for (int k = 0; k < T - 1; k++) {
        // prefetch target[k+1] for x(k+2)  (k+1 <= T-1: always in range)
        float xn = 0.0f;
        if ((j & ~7) == 192) xn = target[(k + 1) * 8 + (j & 7)];

        // ===== Phase alpha: both gate dots, h0 loads shared =====
        u64 a0 = 0, a1 = 0, q0 = 0, q1 = 0, p0 = 0, p1 = 0;
        #pragma unroll
        for (int kk = 0; kk < 16; kk++) {
            ulonglong2 ha = hq0[kk];
            ffma2(a0, whh0p[2 * kk],     ha.x);
            ffma2(a1, whh0p[2 * kk + 1], ha.y);
            ffma2(q0, wih1p[2 * kk],     ha.x);
            ffma2(q1, wih1p[2 * kk + 1], ha.y);
            ulonglong2 hb = hq1[kk];
            ffma2(p0, whh1p[2 * kk],     hb.x);
            ffma2(p1, whh1p[2 * kk + 1], hb.y);
        }
        #pragma unroll
        for (int kk = 0; kk < 4; kk++) ffma2(a0, wxp[kk], sxq[kk]);

        float alo, ahi, glo, ghi;
        unpack2(fadd2(a0, a1), alo, ahi);
        unpack2(fadd2(fadd2(q0, q1), fadd2(p0, p1)), glo, ghi);
        float g0 = dcon + alo + ahi;          // layer0 gate, step k+1
        float g1 = b1c + glo + ghi;           // layer1 gate, step k

        sh_g0[j] = gate_is_g ? tanh_fast(g0) : sigf(g0);
        sh_g1[j] = gate_is_g ? tanh_fast(g1) : sigf(g1);

        // FC head partials for out(k-1): ALL 32 lanes of warp 7, 8 FFMA2 each
        // (stride-4 indexing: lane-uniform h1 broadcast, conflict-free Wcp reads)
        if (j >= 224) {
            int o = j & 7, seg = (j >> 3) & 3;
            u64 f0 = 0, f1 = 0;
            #pragma unroll
            for (int kk = 0; kk < 8; kk++) {
                int idx = kk * 4 + seg;
                ffma2((kk & 1) ? f1 : f0, sh_Wcp[idx * 8 + o], h1q[idx]);
            }
            float flo, fhi; unpack2(fadd2(f0, f1), flo, fhi);
            sh_fcp[seg * 8 + o] = flo + fhi;
        }
        __syncthreads();   // bar 1

        // ===== Phase beta: state updates (parallel across thread groups) =====
        if (j < HID) {
            float ai = sh_g0[j], af = sh_g0[HID + j];
            float ag = sh_g0[128 + j], ao = sh_g0[192 + j];
            c0 = af * c0 + ai * ag;
            sh_h0[j] = ao * tanh_fast(c0);          // h0(k+1)
        } else if (j < 128) {
            int m = j - HID;
            float ai = sh_g1[m], af = sh_g1[HID + m];
            float ag = sh_g1[128 + m], ao = sh_g1[192 + m];
            c1 = af * c1 + ai * ag;
            sh_h1[m] = ao * tanh_fast(c1);          // h1(k)
        } else if (j < 136) {
            if (k > 0) {
                int o = j - 128;
                float s = sh_bc[o] + (sh_fcp[o] + sh_fcp[8 + o])
                                   + (sh_fcp[16 + o] + sh_fcp[24 + o]);
                out[(k - 1) * 8 + o] = rintf(s);
            }
        } else if ((j & ~7) == 192) {
            sh_x[j & 7] = xn;                       // target[k+1] -> x(k+2)
        }
        __syncthreads();   // bar 2
    }

    // ---- peeled final iteration k = T-1: layer1(T-1) only + out(T-2) ----
    {
        u64 p0 = 0, p1 = 0, q0 = 0, q1 = 0;
        #pragma unroll
        for (int kk = 0; kk < 16; kk++) {
            ulonglong2 ha = hq0[kk];
            ffma2(q0, wih1p[2 * kk],     ha.x);
            ffma2(q1, wih1p[2 * kk + 1], ha.y);
            ulonglong2 hb = hq1[kk];
            ffma2(p0, whh1p[2 * kk],     hb.x);
            ffma2(p1, whh1p[2 * kk + 1], hb.y);
        }
        float glo, ghi;
        unpack2(fadd2(fadd2(q0, q1), fadd2(p0, p1)), glo, ghi);
        float g1 = b1c + glo + ghi;
        sh_g1[j] = gate_is_g ? tanh_fast(g1) : sigf(g1);

        if (j >= 224) {   // FC partials for out(T-2) from h1(T-2)
            int o = j & 7, seg = (j >> 3) & 3;
            u64 f0 = 0, f1 = 0;
            #pragma unroll
            for (int kk = 0; kk < 8; kk++) {
                int idx = kk * 4 + seg;
                ffma2((kk & 1) ? f1 : f0, sh_Wcp[idx * 8 + o], h1q[idx]);
            }
            float flo, fhi; unpack2(fadd2(f0, f1), flo, fhi);
            sh_fcp[seg * 8 + o] = flo + fhi;
        }
        __syncthreads();

        if (j >= HID && j < 128) {
            int m = j - HID;
            float ai = sh_g1[m], af = sh_g1[HID + m];
            float ag = sh_g1[128 + m], ao = sh_g1[192 + m];
            c1 = af * c1 + ai * ag;
            sh_h1[m] = ao * tanh_fast(c1);          // h1(T-1)
        } else if (j >= 128 && j < 136 && T > 1) {
            int o = j - 128;
            float s = sh_bc[o] + (sh_fcp[o] + sh_fcp[8 + o])
                               + (sh_fcp[16 + o] + sh_fcp[24 + o]);
            out[(T - 2) * 8 + o] = rintf(s);
        }
        __syncthreads();
    }

    // ---- epilogue: out(T-1) from sh_h1 = h1(T-1), then finals ----
    if (j < 8) {
        u64 acc0 = 0, acc1 = 0;
        #pragma unroll
        for (int kk = 0; kk < 32; kk++)
            ffma2((kk & 1) ? acc1 : acc0, sh_Wcp[kk * 8 + j], h1q[kk]);
        float flo, fhi; unpack2(fadd2(acc0, acc1), flo, fhi);
        out[(T - 1) * 8 + j] = rintf(sh_bc[j] + flo + fhi);
    }
    // finals: h_final = [h0(T-1); h1(T-1)], c_final = [c0(T-1); c1(T-1)]
    if (j < HID) {
        out[T * 8 + j]       = sh_h0[j];
        out[T * 8 + HID + j] = sh_h1[j];
        out[T * 8 + 128 + j] = c0;
    }
    if (j >= HID && j < 128) {
        out[T * 8 + 192 + (j - HID)] = c1;
    }
}

extern "C" void kernel_launch(void* const* d_in, const int* in_sizes, int n_in,
                              void* d_out, int out_size) {
    const float* h0_in  = (const float*)d_in[1];
    const float* c0_in  = (const float*)d_in[2];
    const float* diff   = (const float*)d_in[3];
    const float* target = (const float*)d_in[4];
    const float* W_ih0  = (const float*)d_in[5];
    const float* W_hh0  = (const float*)d_in[6];
    const float* b_ih0  = (const float*)d_in[7];
    const float* b_hh0  = (const float*)d_in[8];
    const float* W_ih1  = (const float*)d_in[9];
    const float* W_hh1  = (const float*)d_in[10];
    const float* b_ih1  = (const float*)d_in[11];
    const float* b_hh1  = (const float*)d_in[12];
    const float* W_hid  = (const float*)d_in[13];
    const float* b_hid  = (const float*)d_in[14];
    const float* W_out  = (const float*)d_in[15];
    const float* b_out  = (const float*)d_in[16];

    int T = in_sizes[4] / 8;

    decoder_lstm_kernel<<<1, 256>>>(
        h0_in, c0_in, diff, target,
        W_ih0, W_hh0, b_ih0, b_hh0,
        W_ih1, W_hh1, b_ih1, b_hh1,
        W_hid, b_hid, W_out, b_out,
        (float*)d_out, T);
}